// round 1
// baseline (speedup 1.0000x reference)
#include <cuda_runtime.h>
#include <math.h>
#include <stdint.h>

// Problem constants (fixed by the dataset)
#define CN   100000      // nodes
#define CE   1600000     // edges
#define CH   128         // hidden / F_IN
#define CM   150000      // cover assignments
#define CKC  60000       // clusters
#define CB   64          // graphs in batch
#define CCOUT 10

// ---------------- scratch (device globals; no allocation) ----------------
__device__ __align__(128) float g_xw  [(size_t)CN * CH];   // x @ W_in
__device__ __align__(128) float g_h   [(size_t)CN * CH];   // agg, then h (in place)
__device__ __align__(128) float g_zn  [(size_t)CN * CH];
__device__ __align__(128) float g_ye  [(size_t)CN * CH];
__device__ __align__(128) float g_xp  [(size_t)CKC * 2 * CH]; // [add | max]
__device__ __align__(128) float g_xws [(size_t)CKC * CH];
__device__ __align__(128) float g_aout[(size_t)CKC * CH];  // aprime out, then hp (in place)
__device__ __align__(128) float g_deg [CN];
__device__ __align__(128) float g_dinv[CN];
__device__ __align__(128) float g_cnt [CN];
__device__ __align__(128) float g_ye1 [CN];
__device__ __align__(128) float g_degp [CKC];
__device__ __align__(128) float g_dinvp[CKC];
__device__ __align__(128) float g_coeff[CE];
__device__ __align__(128) float g_Sh [CB * CH];
__device__ __align__(128) float g_Xh [CB * CH];
__device__ __align__(128) float g_Shp[CB * CH];
__device__ __align__(128) float g_Xhp[CB * CH];
__device__ __align__(128) float g_cc [CB];

// ---------------- utility ----------------
__global__ void k_zero(float4* p, int n4) {
    int i = blockIdx.x * blockDim.x + threadIdx.x;
    int stride = gridDim.x * blockDim.x;
    for (; i < n4; i += stride) p[i] = make_float4(0.f, 0.f, 0.f, 0.f);
}

// ---------------- degree / coeff ----------------
__global__ void k_deg(const int* __restrict__ dst, const float* __restrict__ w, int E) {
    int i = blockIdx.x * blockDim.x + threadIdx.x;
    if (i < E) atomicAdd(&g_deg[dst[i]], w[i]);
}
__global__ void k_dinv(int n) {
    int i = blockIdx.x * blockDim.x + threadIdx.x;
    if (i < n) g_dinv[i] = rsqrtf(g_deg[i] + 1.0f);
}
__global__ void k_coeff(const int* __restrict__ src, const int* __restrict__ dst,
                        const float* __restrict__ w, int E) {
    int i = blockIdx.x * blockDim.x + threadIdx.x;
    if (i < E) g_coeff[i] = w[i] * g_dinv[src[i]] * g_dinv[dst[i]];
}

// ---------------- generic 128-wide row gather->scatter-add ----------------
// Yout[sidx[j]] += coeff[j] * Xin[gidx[j]]   (warp per item, float4 lanes)
__global__ void row_scatter(const int* __restrict__ gidx, const int* __restrict__ sidx,
                            const float* __restrict__ coeff,
                            const float* __restrict__ Xin, float* __restrict__ Yout, int n) {
    int wid = (blockIdx.x * blockDim.x + threadIdx.x) >> 5;
    if (wid >= n) return;
    int lane = threadIdx.x & 31;
    int g = __ldg(gidx + wid);
    int s = __ldg(sidx + wid);
    float c = coeff ? __ldg(coeff + wid) : 1.0f;
    float4 v = __ldg((const float4*)(Xin + (size_t)g * CH) + lane);
    v.x *= c; v.y *= c; v.z *= c; v.w *= c;
    const float* y = Yout + (size_t)s * CH + lane * 4;
    asm volatile("red.global.add.v4.f32 [%0], {%1,%2,%3,%4};"
                 :: "l"(y), "f"(v.x), "f"(v.y), "f"(v.z), "f"(v.w) : "memory");
}

// h = relu(agg + dinv^2 * xw + b_in)  (in place on g_h)
__global__ void k_h(const float* __restrict__ b_in) {
    int n = blockIdx.x, t = threadIdx.x;
    size_t i = (size_t)n * CH + t;
    float d = g_dinv[n];
    float v = g_h[i] + d * d * g_xw[i] + b_in[t];
    g_h[i] = fmaxf(v, 0.0f);
}

// hp = relu(dinvp * (aout + xws) + b_blk)  (in place on g_aout)
__global__ void k_hp(const float* __restrict__ b_blk) {
    int c = blockIdx.x, t = threadIdx.x;
    size_t i = (size_t)c * CH + t;
    float v = g_dinvp[c] * (g_aout[i] + g_xws[i]) + b_blk[t];
    g_aout[i] = fmaxf(v, 0.0f);
}

// ---------------- sorted-label segment sum+max pooling ----------------
// values are >= 0 (post-relu) so max init of 0 is exact.
__global__ void pool_sorted(const float* __restrict__ V, const int* __restrict__ lab,
                            float* __restrict__ S, float* __restrict__ X, int R, int chunk) {
    int t = threadIdx.x;
    long start = (long)blockIdx.x * chunk;
    if (start >= R) return;
    long end = start + chunk; if (end > R) end = R;
    int cur = __ldg(lab + start);
    float s = 0.f, m = 0.f;
    for (long r = start; r < end; r++) {
        int l = __ldg(lab + r);
        if (l != cur) {
            atomicAdd(&S[(size_t)cur * CH + t], s);
            atomicMax((unsigned int*)&X[(size_t)cur * CH + t], __float_as_uint(m));
            s = 0.f; m = 0.f; cur = l;
        }
        float v = __ldg(V + (size_t)r * CH + t);
        s += v; m = fmaxf(m, v);
    }
    atomicAdd(&S[(size_t)cur * CH + t], s);
    atomicMax((unsigned int*)&X[(size_t)cur * CH + t], __float_as_uint(m));
}

// ---------------- cover pooling: xp = [seg_add | seg_max] of h[cover_nodes] ----------------
__global__ void cover_pool(const int* __restrict__ cn, const int* __restrict__ cc,
                           const float* __restrict__ H, float* __restrict__ XP, int M) {
    int wid = (blockIdx.x * blockDim.x + threadIdx.x) >> 5;
    if (wid >= M) return;
    int lane = threadIdx.x & 31;
    int node = __ldg(cn + wid);
    int cl   = __ldg(cc + wid);
    float4 v = __ldg((const float4*)(H + (size_t)node * CH) + lane);
    const float* addp = XP + (size_t)cl * (2 * CH) + lane * 4;
    asm volatile("red.global.add.v4.f32 [%0], {%1,%2,%3,%4};"
                 :: "l"(addp), "f"(v.x), "f"(v.y), "f"(v.z), "f"(v.w) : "memory");
    unsigned int* mx = (unsigned int*)(XP + (size_t)cl * (2 * CH) + CH + lane * 4);
    atomicMax(mx + 0, __float_as_uint(v.x));
    atomicMax(mx + 1, __float_as_uint(v.y));
    atomicMax(mx + 2, __float_as_uint(v.z));
    atomicMax(mx + 3, __float_as_uint(v.w));
}

// ---------------- aprime(ones) scalar chain ----------------
__global__ void k_cnt(const int* __restrict__ cn, int M) {
    int i = blockIdx.x * blockDim.x + threadIdx.x;
    if (i < M) atomicAdd(&g_cnt[cn[i]], 1.0f);
}
__global__ void k_ye1(const int* __restrict__ src, const int* __restrict__ dst,
                      const float* __restrict__ w, int E) {
    int i = blockIdx.x * blockDim.x + threadIdx.x;
    if (i < E) atomicAdd(&g_ye1[dst[i]], w[i] * g_cnt[src[i]]);
}
__global__ void k_degp(const int* __restrict__ cn, const int* __restrict__ cc, int M) {
    int i = blockIdx.x * blockDim.x + threadIdx.x;
    if (i < M) atomicAdd(&g_degp[cc[i]], g_ye1[cn[i]]);
}
__global__ void k_dinvp(int n) {
    int i = blockIdx.x * blockDim.x + threadIdx.x;
    if (i < n) g_dinvp[i] = rsqrtf(g_degp[i] + 1.0f);
}

// ---------------- cluster-batch counts (single block, smem) ----------------
__global__ void k_ccounts(const int* __restrict__ cb, int KC) {
    __shared__ float s[CB];
    int t = threadIdx.x;
    if (t < CB) s[t] = 0.f;
    __syncthreads();
    for (int i = t; i < KC; i += blockDim.x) atomicAdd(&s[cb[i]], 1.0f);
    __syncthreads();
    if (t < CB) g_cc[t] = s[t];
}

// ---------------- SGEMM: C[M,128] = A[M,K] @ B[K,128], optional row scale ----------------
__global__ __launch_bounds__(256)
void sgemm128(const float* __restrict__ A, const float* __restrict__ B,
              float* __restrict__ C, int M, int K, const float* __restrict__ rowscale) {
    const int BK = 8;
    __shared__ float As[BK][128];
    __shared__ float Bs[BK][128];
    int tid = threadIdx.x;
    int tx = tid & 15, ty = tid >> 4;   // 16 x 16
    int rowBase = blockIdx.x * 128;
    float acc[8][8];
    #pragma unroll
    for (int i = 0; i < 8; i++)
        #pragma unroll
        for (int j = 0; j < 8; j++) acc[i][j] = 0.f;

    int aRow = tid >> 1;
    int aK   = (tid & 1) * 4;
    int bK   = tid >> 5;
    int bC   = (tid & 31) * 4;

    for (int kt = 0; kt < K; kt += BK) {
        int gr = rowBase + aRow;
        float4 av = make_float4(0.f, 0.f, 0.f, 0.f);
        if (gr < M) av = *(const float4*)(A + (size_t)gr * K + kt + aK);
        As[aK + 0][aRow] = av.x; As[aK + 1][aRow] = av.y;
        As[aK + 2][aRow] = av.z; As[aK + 3][aRow] = av.w;
        float4 bv = *(const float4*)(B + (size_t)(kt + bK) * 128 + bC);
        *(float4*)&Bs[bK][bC] = bv;
        __syncthreads();
        #pragma unroll
        for (int k = 0; k < BK; k++) {
            float ar[8], br[8];
            #pragma unroll
            for (int i = 0; i < 8; i++) ar[i] = As[k][ty * 8 + i];
            #pragma unroll
            for (int j = 0; j < 8; j++) br[j] = Bs[k][tx * 8 + j];
            #pragma unroll
            for (int i = 0; i < 8; i++)
                #pragma unroll
                for (int j = 0; j < 8; j++) acc[i][j] += ar[i] * br[j];
        }
        __syncthreads();
    }
    #pragma unroll
    for (int i = 0; i < 8; i++) {
        int r = rowBase + ty * 8 + i;
        if (r >= M) break;
        float s = rowscale ? rowscale[r] : 1.0f;
        float* cp = C + (size_t)r * 128 + tx * 8;
        float4 v0 = make_float4(acc[i][0] * s, acc[i][1] * s, acc[i][2] * s, acc[i][3] * s);
        float4 v1 = make_float4(acc[i][4] * s, acc[i][5] * s, acc[i][6] * s, acc[i][7] * s);
        *(float4*)(cp + 0) = v0;
        *(float4*)(cp + 4) = v1;
    }
}

// ---------------- final BN + MLP + softmax ----------------
__global__ void k_mlp(const float* __restrict__ gamma, const float* __restrict__ beta,
                      const float* __restrict__ mu, const float* __restrict__ var,
                      const float* __restrict__ W1, const float* __restrict__ b1,
                      const float* __restrict__ W2, const float* __restrict__ b2,
                      float* __restrict__ out) {
    __shared__ float zs[4 * CH];
    __shared__ float y1s[CH];
    __shared__ float lg[CCOUT];
    int b = blockIdx.x, t = threadIdx.x;
    float inv_cc = 1.0f / g_cc[b];
    float raws[4];
    raws[0] = g_Sh [b * CH + t];
    raws[1] = g_Xh [b * CH + t];
    raws[2] = g_Shp[b * CH + t] * inv_cc;
    raws[3] = g_Xhp[b * CH + t];
    #pragma unroll
    for (int seg = 0; seg < 4; seg++) {
        int idx = seg * CH + t;
        zs[idx] = (raws[seg] - mu[idx]) * rsqrtf(var[idx] + 1e-5f) * gamma[idx] + beta[idx];
    }
    __syncthreads();
    float acc = b1[t];
    for (int k = 0; k < 4 * CH; k++) acc += zs[k] * W1[(size_t)k * CH + t];
    y1s[t] = fmaxf(acc, 0.f);
    __syncthreads();
    if (t < CCOUT) {
        float a = b2[t];
        for (int j = 0; j < CH; j++) a += y1s[j] * W2[j * CCOUT + t];
        lg[t] = a;
    }
    __syncthreads();
    if (t == 0) {
        float mx = lg[0];
        for (int c = 1; c < CCOUT; c++) mx = fmaxf(mx, lg[c]);
        float e[CCOUT]; float sum = 0.f;
        for (int c = 0; c < CCOUT; c++) { e[c] = expf(lg[c] - mx); sum += e[c]; }
        for (int c = 0; c < CCOUT; c++) out[b * CCOUT + c] = e[c] / sum;
    }
}

// ---------------- host ----------------
static inline void zero_buf(float* p, long n) {
    int n4 = (int)(n / 4);
    int grid = (n4 + 255) / 256; if (grid > 4096) grid = 4096;
    k_zero<<<grid, 256>>>((float4*)p, n4);
}

extern "C" void kernel_launch(void* const* d_in, const int* in_sizes, int n_in,
                              void* d_out, int out_size) {
    const float* x     = (const float*)d_in[0];
    const int*   ei    = (const int*)  d_in[1];
    const float* w     = (const float*)d_in[2];
    const int*   batch = (const int*)  d_in[3];
    const int*   cn    = (const int*)  d_in[4];
    const int*   cc    = (const int*)  d_in[5];
    const int*   cb    = (const int*)  d_in[6];
    const float* W_in  = (const float*)d_in[7];
    const float* b_in  = (const float*)d_in[8];
    const float* W_blk = (const float*)d_in[9];
    const float* b_blk = (const float*)d_in[10];
    const float* gam   = (const float*)d_in[11];
    const float* bet   = (const float*)d_in[12];
    const float* mu    = (const float*)d_in[13];
    const float* var   = (const float*)d_in[14];
    const float* W1    = (const float*)d_in[15];
    const float* b1    = (const float*)d_in[16];
    const float* W2    = (const float*)d_in[17];
    const float* b2    = (const float*)d_in[18];
    float* out = (float*)d_out;

    int E  = in_sizes[2];
    int N  = in_sizes[3];
    int M  = in_sizes[4];
    int KC = in_sizes[6];
    const int* src = ei;
    const int* dst = ei + E;

    float *p_xw, *p_h, *p_zn, *p_ye, *p_xp, *p_xws, *p_aout;
    float *p_deg, *p_cnt, *p_ye1, *p_degp, *p_dinvp, *p_coeff;
    float *p_Sh, *p_Xh, *p_Shp, *p_Xhp;
    cudaGetSymbolAddress((void**)&p_xw,   g_xw);
    cudaGetSymbolAddress((void**)&p_h,    g_h);
    cudaGetSymbolAddress((void**)&p_zn,   g_zn);
    cudaGetSymbolAddress((void**)&p_ye,   g_ye);
    cudaGetSymbolAddress((void**)&p_xp,   g_xp);
    cudaGetSymbolAddress((void**)&p_xws,  g_xws);
    cudaGetSymbolAddress((void**)&p_aout, g_aout);
    cudaGetSymbolAddress((void**)&p_deg,  g_deg);
    cudaGetSymbolAddress((void**)&p_cnt,  g_cnt);
    cudaGetSymbolAddress((void**)&p_ye1,  g_ye1);
    cudaGetSymbolAddress((void**)&p_degp, g_degp);
    cudaGetSymbolAddress((void**)&p_dinvp,g_dinvp);
    cudaGetSymbolAddress((void**)&p_coeff,g_coeff);
    cudaGetSymbolAddress((void**)&p_Sh,   g_Sh);
    cudaGetSymbolAddress((void**)&p_Xh,   g_Xh);
    cudaGetSymbolAddress((void**)&p_Shp,  g_Shp);
    cudaGetSymbolAddress((void**)&p_Xhp,  g_Xhp);

    // ---- zero accumulators ----
    zero_buf(p_h,   (long)N * CH);
    zero_buf(p_zn,  (long)N * CH);
    zero_buf(p_ye,  (long)N * CH);
    zero_buf(p_xp,  (long)KC * 2 * CH);
    zero_buf(p_aout,(long)KC * CH);
    zero_buf(p_deg, N);
    zero_buf(p_cnt, N);
    zero_buf(p_ye1, N);
    zero_buf(p_degp,KC);
    zero_buf(p_Sh,  CB * CH);
    zero_buf(p_Xh,  CB * CH);
    zero_buf(p_Shp, CB * CH);
    zero_buf(p_Xhp, CB * CH);

    // ---- degrees & normalization ----
    k_deg  <<<(E + 255) / 256, 256>>>(dst, w, E);
    k_dinv <<<(N + 255) / 256, 256>>>(N);

    // ---- xw = x @ W_in ----
    sgemm128<<<(N + 127) / 128, 256>>>(x, W_in, p_xw, N, CH, nullptr);

    // ---- edge propagation pass 1 ----
    k_coeff<<<(E + 255) / 256, 256>>>(src, dst, w, E);
    row_scatter<<<(int)(((long)E * 32 + 255) / 256), 256>>>(src, dst, p_coeff, p_xw, p_h, E);
    k_h<<<N, CH>>>(b_in);

    // ---- node-level pooling (sum + max over batch) ----
    pool_sorted<<<(N + 511) / 512, CH>>>(p_h, batch, p_Sh, p_Xh, N, 512);

    // ---- cover pooling: xp = [add | max] ----
    cover_pool<<<(int)(((long)M * 32 + 255) / 256), 256>>>(cn, cc, p_h, p_xp, M);

    // ---- aprime(ones) -> degp -> dinvp ----
    k_cnt  <<<(M + 255) / 256, 256>>>(cn, M);
    k_ye1  <<<(E + 255) / 256, 256>>>(src, dst, w, E);
    k_degp <<<(M + 255) / 256, 256>>>(cn, cc, M);
    k_dinvp<<<(KC + 255) / 256, 256>>>(KC);

    // ---- xws = dinvp * (xp @ W_blk) ----
    sgemm128<<<(KC + 127) / 128, 256>>>(p_xp, W_blk, p_xws, KC, 2 * CH, p_dinvp);

    // ---- aprime(xws): zn = C xws ; ye = A zn ; aout = C^T ye ----
    row_scatter<<<(int)(((long)M * 32 + 255) / 256), 256>>>(cc, cn, nullptr, p_xws, p_zn, M);
    row_scatter<<<(int)(((long)E * 32 + 255) / 256), 256>>>(src, dst, w, p_zn, p_ye, E);
    row_scatter<<<(int)(((long)M * 32 + 255) / 256), 256>>>(cn, cc, nullptr, p_ye, p_aout, M);

    // ---- hp = relu(dinvp*(aout+xws)+b_blk) (in place into aout) ----
    k_hp<<<KC, CH>>>(b_blk);

    // ---- cluster pooling (sum + max over cluster_batch) + counts ----
    k_ccounts<<<1, 256>>>(cb, KC);
    pool_sorted<<<(KC + 511) / 512, CH>>>(p_aout, cb, p_Shp, p_Xhp, KC, 512);

    // ---- BN + MLP + softmax ----
    k_mlp<<<CB, CH>>>(gam, bet, mu, var, W1, b1, W2, b2, out);
}

// round 2
// speedup vs baseline: 1.1026x; 1.1026x over previous
#include <cuda_runtime.h>
#include <math.h>
#include <stdint.h>

// Problem constants (fixed by the dataset)
#define CN   100000      // nodes
#define CE   1600000     // edges
#define CH   128         // hidden / F_IN
#define CM   150000      // cover assignments
#define CKC  60000       // clusters
#define CB   64          // graphs in batch
#define CCOUT 10

// ---------------- scratch (device globals; no allocation) ----------------
__device__ __align__(128) float g_xw  [(size_t)CN * CH];   // x @ W_in
__device__ __align__(128) float g_h   [(size_t)CN * CH];   // relu(gcn1)
__device__ __align__(128) float g_zn  [(size_t)CN * CH];
__device__ __align__(128) float g_ye  [(size_t)CN * CH];
__device__ __align__(128) float g_xp  [(size_t)CKC * 2 * CH]; // [add | max]
__device__ __align__(128) float g_xws [(size_t)CKC * CH];
__device__ __align__(128) float g_hp  [(size_t)CKC * CH];
__device__ __align__(128) float g_dinv [CN];
__device__ __align__(128) float g_ye1  [CN];
__device__ __align__(128) float g_dinvp[CKC];
__device__ __align__(128) float g_Sh [CB * CH];
__device__ __align__(128) float g_Xh [CB * CH];
__device__ __align__(128) float g_Shp[CB * CH];
__device__ __align__(128) float g_Xhp[CB * CH];
__device__ __align__(128) float g_cc [CB];

// CSR-E: dst -> (src, w)
__device__ __align__(128) int  g_cntE[CN];
__device__ __align__(128) int  g_offE[CN + 1];
__device__ __align__(128) int  g_curE[CN];
__device__ __align__(128) int2 g_edges[CE];
// CSR-C: cluster -> cover_node entries
__device__ __align__(128) int  g_cntC[CKC];
__device__ __align__(128) int  g_offC[CKC + 1];
__device__ __align__(128) int  g_curC[CKC];
__device__ __align__(128) int  g_cnC [CM];
// CSR-N: node -> cover_cluster entries
__device__ __align__(128) int  g_cntN[CN];
__device__ __align__(128) int  g_offN[CN + 1];
__device__ __align__(128) int  g_curN[CN];
__device__ __align__(128) int  g_ccN [CM];

// ---------------- utility ----------------
__global__ void k_zero(float4* p, int n4) {
    int i = blockIdx.x * blockDim.x + threadIdx.x;
    int stride = gridDim.x * blockDim.x;
    for (; i < n4; i += stride) p[i] = make_float4(0.f, 0.f, 0.f, 0.f);
}

// ---------------- CSR build ----------------
__global__ void k_hist(const int* __restrict__ idx, int* __restrict__ cnt, int n) {
    int i = blockIdx.x * blockDim.x + threadIdx.x;
    if (i < n) atomicAdd(&cnt[idx[i]], 1);
}

// single-block exclusive scan (n <= ~2M, 1024 threads, chunked)
__global__ __launch_bounds__(1024)
void k_scan_excl(const int* __restrict__ cnt, int* __restrict__ off,
                 int* __restrict__ cur, int n) {
    __shared__ int ssum[1024];
    int t = threadIdx.x;
    int chunk = (n + 1023) / 1024;
    int beg = t * chunk;
    int end = beg + chunk; if (end > n) end = n;
    int s = 0;
    for (int i = beg; i < end; i++) s += cnt[i];
    ssum[t] = s;
    __syncthreads();
    for (int d = 1; d < 1024; d <<= 1) {
        int v = (t >= d) ? ssum[t - d] : 0;
        __syncthreads();
        ssum[t] += v;
        __syncthreads();
    }
    int prefix = (t == 0) ? 0 : ssum[t - 1];
    for (int i = beg; i < end; i++) {
        off[i] = prefix;
        cur[i] = prefix;
        prefix += cnt[i];
    }
    if (end == n) off[n] = prefix;   // benign multi-write of total
}

__global__ void k_fillE(const int* __restrict__ src, const int* __restrict__ dst,
                        const float* __restrict__ w, int E) {
    int i = blockIdx.x * blockDim.x + threadIdx.x;
    if (i >= E) return;
    int pos = atomicAdd(&g_curE[dst[i]], 1);
    g_edges[pos] = make_int2(src[i], __float_as_int(w[i]));
}
__global__ void k_fillC(const int* __restrict__ cn, const int* __restrict__ cc, int M) {
    int i = blockIdx.x * blockDim.x + threadIdx.x;
    if (i >= M) return;
    int pos = atomicAdd(&g_curC[cc[i]], 1);
    g_cnC[pos] = cn[i];
}
__global__ void k_fillN(const int* __restrict__ cn, const int* __restrict__ cc, int M) {
    int i = blockIdx.x * blockDim.x + threadIdx.x;
    if (i >= M) return;
    int pos = atomicAdd(&g_curN[cn[i]], 1);
    g_ccN[pos] = cc[i];
}

// ---------------- degree / dinv from CSR-E (thread per node) ----------------
__global__ void k_deg_dinv(int N) {
    int n = blockIdx.x * blockDim.x + threadIdx.x;
    if (n >= N) return;
    int beg = g_offE[n], end = g_offE[n + 1];
    float s = 0.f;
    for (int e = beg; e < end; e++) s += __int_as_float(__ldg(&g_edges[e].y));
    g_dinv[n] = rsqrtf(s + 1.0f);
}

// ---------------- GCN pass 1 gather: h = relu(sum coeff*xw[src] + dinv^2*xw + b) ----------------
__global__ void gather_gcn1(const float* __restrict__ b_in, int N) {
    int wid = (blockIdx.x * blockDim.x + threadIdx.x) >> 5;
    if (wid >= N) return;
    int lane = threadIdx.x & 31;
    int beg = __ldg(&g_offE[wid]), end = __ldg(&g_offE[wid + 1]);
    float dn = __ldg(&g_dinv[wid]);
    float4 acc = make_float4(0.f, 0.f, 0.f, 0.f);
    int e = beg;
    for (; e + 2 <= end; e += 2) {
        int2 e0 = __ldg(&g_edges[e]);
        int2 e1 = __ldg(&g_edges[e + 1]);
        float c0 = __int_as_float(e0.y) * dn * __ldg(&g_dinv[e0.x]);
        float c1 = __int_as_float(e1.y) * dn * __ldg(&g_dinv[e1.x]);
        float4 v0 = __ldg((const float4*)(g_xw + (size_t)e0.x * CH) + lane);
        float4 v1 = __ldg((const float4*)(g_xw + (size_t)e1.x * CH) + lane);
        acc.x = fmaf(c0, v0.x, acc.x); acc.y = fmaf(c0, v0.y, acc.y);
        acc.z = fmaf(c0, v0.z, acc.z); acc.w = fmaf(c0, v0.w, acc.w);
        acc.x = fmaf(c1, v1.x, acc.x); acc.y = fmaf(c1, v1.y, acc.y);
        acc.z = fmaf(c1, v1.z, acc.z); acc.w = fmaf(c1, v1.w, acc.w);
    }
    if (e < end) {
        int2 e0 = __ldg(&g_edges[e]);
        float c0 = __int_as_float(e0.y) * dn * __ldg(&g_dinv[e0.x]);
        float4 v0 = __ldg((const float4*)(g_xw + (size_t)e0.x * CH) + lane);
        acc.x = fmaf(c0, v0.x, acc.x); acc.y = fmaf(c0, v0.y, acc.y);
        acc.z = fmaf(c0, v0.z, acc.z); acc.w = fmaf(c0, v0.w, acc.w);
    }
    float4 xv = __ldg((const float4*)(g_xw + (size_t)wid * CH) + lane);
    float4 bv = __ldg((const float4*)b_in + lane);
    float dd = dn * dn;
    acc.x = fmaxf(fmaf(dd, xv.x, acc.x) + bv.x, 0.f);
    acc.y = fmaxf(fmaf(dd, xv.y, acc.y) + bv.y, 0.f);
    acc.z = fmaxf(fmaf(dd, xv.z, acc.z) + bv.z, 0.f);
    acc.w = fmaxf(fmaf(dd, xv.w, acc.w) + bv.w, 0.f);
    *((float4*)(g_h + (size_t)wid * CH) + lane) = acc;
}

// ---------------- GCN pass 2 gather: ye = sum w*zn[src] ----------------
__global__ void gather_ye(int N) {
    int wid = (blockIdx.x * blockDim.x + threadIdx.x) >> 5;
    if (wid >= N) return;
    int lane = threadIdx.x & 31;
    int beg = __ldg(&g_offE[wid]), end = __ldg(&g_offE[wid + 1]);
    float4 acc = make_float4(0.f, 0.f, 0.f, 0.f);
    int e = beg;
    for (; e + 2 <= end; e += 2) {
        int2 e0 = __ldg(&g_edges[e]);
        int2 e1 = __ldg(&g_edges[e + 1]);
        float c0 = __int_as_float(e0.y);
        float c1 = __int_as_float(e1.y);
        float4 v0 = __ldg((const float4*)(g_zn + (size_t)e0.x * CH) + lane);
        float4 v1 = __ldg((const float4*)(g_zn + (size_t)e1.x * CH) + lane);
        acc.x = fmaf(c0, v0.x, acc.x); acc.y = fmaf(c0, v0.y, acc.y);
        acc.z = fmaf(c0, v0.z, acc.z); acc.w = fmaf(c0, v0.w, acc.w);
        acc.x = fmaf(c1, v1.x, acc.x); acc.y = fmaf(c1, v1.y, acc.y);
        acc.z = fmaf(c1, v1.z, acc.z); acc.w = fmaf(c1, v1.w, acc.w);
    }
    if (e < end) {
        int2 e0 = __ldg(&g_edges[e]);
        float c0 = __int_as_float(e0.y);
        float4 v0 = __ldg((const float4*)(g_zn + (size_t)e0.x * CH) + lane);
        acc.x = fmaf(c0, v0.x, acc.x); acc.y = fmaf(c0, v0.y, acc.y);
        acc.z = fmaf(c0, v0.z, acc.z); acc.w = fmaf(c0, v0.w, acc.w);
    }
    *((float4*)(g_ye + (size_t)wid * CH) + lane) = acc;
}

// ---------------- cover pooling gather: xp[c] = [sum h[cn], max h[cn]] ----------------
__global__ void gather_xp(int KC) {
    int wid = (blockIdx.x * blockDim.x + threadIdx.x) >> 5;
    if (wid >= KC) return;
    int lane = threadIdx.x & 31;
    int beg = __ldg(&g_offC[wid]), end = __ldg(&g_offC[wid + 1]);
    float4 add = make_float4(0.f, 0.f, 0.f, 0.f);
    float4 mx  = make_float4(0.f, 0.f, 0.f, 0.f);   // h >= 0 post-relu
    for (int j = beg; j < end; j++) {
        int node = __ldg(&g_cnC[j]);
        float4 v = __ldg((const float4*)(g_h + (size_t)node * CH) + lane);
        add.x += v.x; add.y += v.y; add.z += v.z; add.w += v.w;
        mx.x = fmaxf(mx.x, v.x); mx.y = fmaxf(mx.y, v.y);
        mx.z = fmaxf(mx.z, v.z); mx.w = fmaxf(mx.w, v.w);
    }
    float* xp = g_xp + (size_t)wid * (2 * CH);
    *((float4*)xp + lane) = add;
    *((float4*)(xp + CH) + lane) = mx;
}

// ---------------- zn = C xws gather (warp per node over CSR-N) ----------------
__global__ void gather_zn(int N) {
    int wid = (blockIdx.x * blockDim.x + threadIdx.x) >> 5;
    if (wid >= N) return;
    int lane = threadIdx.x & 31;
    int beg = __ldg(&g_offN[wid]), end = __ldg(&g_offN[wid + 1]);
    float4 acc = make_float4(0.f, 0.f, 0.f, 0.f);
    for (int j = beg; j < end; j++) {
        int cl = __ldg(&g_ccN[j]);
        float4 v = __ldg((const float4*)(g_xws + (size_t)cl * CH) + lane);
        acc.x += v.x; acc.y += v.y; acc.z += v.z; acc.w += v.w;
    }
    *((float4*)(g_zn + (size_t)wid * CH) + lane) = acc;
}

// ---------------- hp = relu(dinvp*(C^T ye + xws) + b_blk) (warp per cluster) ----------------
__global__ void gather_hp(const float* __restrict__ b_blk, int KC) {
    int wid = (blockIdx.x * blockDim.x + threadIdx.x) >> 5;
    if (wid >= KC) return;
    int lane = threadIdx.x & 31;
    int beg = __ldg(&g_offC[wid]), end = __ldg(&g_offC[wid + 1]);
    float4 acc = make_float4(0.f, 0.f, 0.f, 0.f);
    for (int j = beg; j < end; j++) {
        int node = __ldg(&g_cnC[j]);
        float4 v = __ldg((const float4*)(g_ye + (size_t)node * CH) + lane);
        acc.x += v.x; acc.y += v.y; acc.z += v.z; acc.w += v.w;
    }
    float dp = __ldg(&g_dinvp[wid]);
    float4 xv = __ldg((const float4*)(g_xws + (size_t)wid * CH) + lane);
    float4 bv = __ldg((const float4*)b_blk + lane);
    acc.x = fmaxf(fmaf(dp, acc.x + xv.x, bv.x), 0.f);
    acc.y = fmaxf(fmaf(dp, acc.y + xv.y, bv.y), 0.f);
    acc.z = fmaxf(fmaf(dp, acc.z + xv.z, bv.z), 0.f);
    acc.w = fmaxf(fmaf(dp, acc.w + xv.w, bv.w), 0.f);
    *((float4*)(g_hp + (size_t)wid * CH) + lane) = acc;
}

// ---------------- aprime(ones) scalar chain (gather form) ----------------
// ye1[n] = sum_e w_e * cntN[src_e]  (thread per node over CSR-E)
__global__ void k_ye1g(int N) {
    int n = blockIdx.x * blockDim.x + threadIdx.x;
    if (n >= N) return;
    int beg = g_offE[n], end = g_offE[n + 1];
    float s = 0.f;
    for (int e = beg; e < end; e++) {
        int2 ed = __ldg(&g_edges[e]);
        s += __int_as_float(ed.y) * (float)__ldg(&g_cntN[ed.x]);
    }
    g_ye1[n] = s;
}
// dinvp[c] = rsqrt(sum ye1[cnC[j]] + 1)  (thread per cluster over CSR-C)
__global__ void k_dinvp_g(int KC) {
    int c = blockIdx.x * blockDim.x + threadIdx.x;
    if (c >= KC) return;
    int beg = g_offC[c], end = g_offC[c + 1];
    float s = 0.f;
    for (int j = beg; j < end; j++) s += __ldg(&g_ye1[g_cnC[j]]);
    g_dinvp[c] = rsqrtf(s + 1.0f);
}

// ---------------- sorted-label segment sum+max pooling ----------------
__global__ void pool_sorted(const float* __restrict__ V, const int* __restrict__ lab,
                            float* __restrict__ S, float* __restrict__ X, int R, int chunk) {
    int t = threadIdx.x;
    long start = (long)blockIdx.x * chunk;
    if (start >= R) return;
    long end = start + chunk; if (end > R) end = R;
    int cur = __ldg(lab + start);
    float s = 0.f, m = 0.f;
    for (long r = start; r < end; r++) {
        int l = __ldg(lab + r);
        if (l != cur) {
            atomicAdd(&S[(size_t)cur * CH + t], s);
            atomicMax((unsigned int*)&X[(size_t)cur * CH + t], __float_as_uint(m));
            s = 0.f; m = 0.f; cur = l;
        }
        float v = __ldg(V + (size_t)r * CH + t);
        s += v; m = fmaxf(m, v);
    }
    atomicAdd(&S[(size_t)cur * CH + t], s);
    atomicMax((unsigned int*)&X[(size_t)cur * CH + t], __float_as_uint(m));
}

// ---------------- cluster-batch counts ----------------
__global__ void k_ccounts(const int* __restrict__ cb, int KC) {
    __shared__ float s[CB];
    int t = threadIdx.x;
    if (t < CB) s[t] = 0.f;
    __syncthreads();
    for (int i = t; i < KC; i += blockDim.x) atomicAdd(&s[cb[i]], 1.0f);
    __syncthreads();
    if (t < CB) g_cc[t] = s[t];
}

// ---------------- SGEMM: C[M,128] = A[M,K] @ B[K,128], optional row scale ----------------
__global__ __launch_bounds__(256)
void sgemm128(const float* __restrict__ A, const float* __restrict__ B,
              float* __restrict__ C, int M, int K, const float* __restrict__ rowscale) {
    const int BK = 8;
    __shared__ float As[BK][128];
    __shared__ float Bs[BK][128];
    int tid = threadIdx.x;
    int tx = tid & 15, ty = tid >> 4;
    int rowBase = blockIdx.x * 128;
    float acc[8][8];
    #pragma unroll
    for (int i = 0; i < 8; i++)
        #pragma unroll
        for (int j = 0; j < 8; j++) acc[i][j] = 0.f;

    int aRow = tid >> 1;
    int aK   = (tid & 1) * 4;
    int bK   = tid >> 5;
    int bC   = (tid & 31) * 4;

    for (int kt = 0; kt < K; kt += BK) {
        int gr = rowBase + aRow;
        float4 av = make_float4(0.f, 0.f, 0.f, 0.f);
        if (gr < M) av = *(const float4*)(A + (size_t)gr * K + kt + aK);
        As[aK + 0][aRow] = av.x; As[aK + 1][aRow] = av.y;
        As[aK + 2][aRow] = av.z; As[aK + 3][aRow] = av.w;
        float4 bv = *(const float4*)(B + (size_t)(kt + bK) * 128 + bC);
        *(float4*)&Bs[bK][bC] = bv;
        __syncthreads();
        #pragma unroll
        for (int k = 0; k < BK; k++) {
            float ar[8], br[8];
            #pragma unroll
            for (int i = 0; i < 8; i++) ar[i] = As[k][ty * 8 + i];
            #pragma unroll
            for (int j = 0; j < 8; j++) br[j] = Bs[k][tx * 8 + j];
            #pragma unroll
            for (int i = 0; i < 8; i++)
                #pragma unroll
                for (int j = 0; j < 8; j++) acc[i][j] += ar[i] * br[j];
        }
        __syncthreads();
    }
    #pragma unroll
    for (int i = 0; i < 8; i++) {
        int r = rowBase + ty * 8 + i;
        if (r >= M) break;
        float s = rowscale ? rowscale[r] : 1.0f;
        float* cp = C + (size_t)r * 128 + tx * 8;
        float4 v0 = make_float4(acc[i][0] * s, acc[i][1] * s, acc[i][2] * s, acc[i][3] * s);
        float4 v1 = make_float4(acc[i][4] * s, acc[i][5] * s, acc[i][6] * s, acc[i][7] * s);
        *(float4*)(cp + 0) = v0;
        *(float4*)(cp + 4) = v1;
    }
}

// ---------------- final BN + MLP + softmax ----------------
__global__ void k_mlp(const float* __restrict__ gamma, const float* __restrict__ beta,
                      const float* __restrict__ mu, const float* __restrict__ var,
                      const float* __restrict__ W1, const float* __restrict__ b1,
                      const float* __restrict__ W2, const float* __restrict__ b2,
                      float* __restrict__ out) {
    __shared__ float zs[4 * CH];
    __shared__ float y1s[CH];
    __shared__ float lg[CCOUT];
    int b = blockIdx.x, t = threadIdx.x;
    float inv_cc = 1.0f / g_cc[b];
    float raws[4];
    raws[0] = g_Sh [b * CH + t];
    raws[1] = g_Xh [b * CH + t];
    raws[2] = g_Shp[b * CH + t] * inv_cc;
    raws[3] = g_Xhp[b * CH + t];
    #pragma unroll
    for (int seg = 0; seg < 4; seg++) {
        int idx = seg * CH + t;
        zs[idx] = (raws[seg] - mu[idx]) * rsqrtf(var[idx] + 1e-5f) * gamma[idx] + beta[idx];
    }
    __syncthreads();
    float acc = b1[t];
    for (int k = 0; k < 4 * CH; k++) acc += zs[k] * W1[(size_t)k * CH + t];
    y1s[t] = fmaxf(acc, 0.f);
    __syncthreads();
    if (t < CCOUT) {
        float a = b2[t];
        for (int j = 0; j < CH; j++) a += y1s[j] * W2[j * CCOUT + t];
        lg[t] = a;
    }
    __syncthreads();
    if (t == 0) {
        float mx = lg[0];
        for (int c = 1; c < CCOUT; c++) mx = fmaxf(mx, lg[c]);
        float e[CCOUT]; float sum = 0.f;
        for (int c = 0; c < CCOUT; c++) { e[c] = expf(lg[c] - mx); sum += e[c]; }
        for (int c = 0; c < CCOUT; c++) out[b * CCOUT + c] = e[c] / sum;
    }
}

// ---------------- host ----------------
static inline void zero_f(float* p, long n) {
    int n4 = (int)(n / 4);
    int grid = (n4 + 255) / 256; if (grid > 4096) grid = 4096;
    if (n4 > 0) k_zero<<<grid, 256>>>((float4*)p, n4);
}
static inline void zero_i(int* p, long n) { zero_f((float*)p, n); }

extern "C" void kernel_launch(void* const* d_in, const int* in_sizes, int n_in,
                              void* d_out, int out_size) {
    const float* x     = (const float*)d_in[0];
    const int*   ei    = (const int*)  d_in[1];
    const float* w     = (const float*)d_in[2];
    const int*   batch = (const int*)  d_in[3];
    const int*   cn    = (const int*)  d_in[4];
    const int*   cc    = (const int*)  d_in[5];
    const int*   cb    = (const int*)  d_in[6];
    const float* W_in  = (const float*)d_in[7];
    const float* b_in  = (const float*)d_in[8];
    const float* W_blk = (const float*)d_in[9];
    const float* b_blk = (const float*)d_in[10];
    const float* gam   = (const float*)d_in[11];
    const float* bet   = (const float*)d_in[12];
    const float* mu    = (const float*)d_in[13];
    const float* var   = (const float*)d_in[14];
    const float* W1    = (const float*)d_in[15];
    const float* b1    = (const float*)d_in[16];
    const float* W2    = (const float*)d_in[17];
    const float* b2    = (const float*)d_in[18];
    float* out = (float*)d_out;

    int E  = in_sizes[2];
    int N  = in_sizes[3];
    int M  = in_sizes[4];
    int KC = in_sizes[6];
    const int* src = ei;
    const int* dst = ei + E;

    float *p_xw, *p_xp, *p_xws, *p_h, *p_hp;
    float *p_Sh, *p_Xh, *p_Shp, *p_Xhp;
    int *p_cntE, *p_offE, *p_curE, *p_cntC, *p_offC, *p_curC, *p_cntN, *p_offN, *p_curN;
    float *p_dinvp;
    cudaGetSymbolAddress((void**)&p_xw,   g_xw);
    cudaGetSymbolAddress((void**)&p_xp,   g_xp);
    cudaGetSymbolAddress((void**)&p_xws,  g_xws);
    cudaGetSymbolAddress((void**)&p_h,    g_h);
    cudaGetSymbolAddress((void**)&p_hp,   g_hp);
    cudaGetSymbolAddress((void**)&p_Sh,   g_Sh);
    cudaGetSymbolAddress((void**)&p_Xh,   g_Xh);
    cudaGetSymbolAddress((void**)&p_Shp,  g_Shp);
    cudaGetSymbolAddress((void**)&p_Xhp,  g_Xhp);
    cudaGetSymbolAddress((void**)&p_cntE, g_cntE);
    cudaGetSymbolAddress((void**)&p_offE, g_offE);
    cudaGetSymbolAddress((void**)&p_curE, g_curE);
    cudaGetSymbolAddress((void**)&p_cntC, g_cntC);
    cudaGetSymbolAddress((void**)&p_offC, g_offC);
    cudaGetSymbolAddress((void**)&p_curC, g_curC);
    cudaGetSymbolAddress((void**)&p_cntN, g_cntN);
    cudaGetSymbolAddress((void**)&p_offN, g_offN);
    cudaGetSymbolAddress((void**)&p_curN, g_curN);
    cudaGetSymbolAddress((void**)&p_dinvp, g_dinvp);

    const int T = 256;
    int warpsN  = (int)(((long)N * 32 + T - 1) / T);
    int warpsKC = (int)(((long)KC * 32 + T - 1) / T);

    // ---- zero count arrays + pooling accumulators (tiny) ----
    zero_i(p_cntE, N);
    zero_i(p_cntC, KC);
    zero_i(p_cntN, N);
    zero_f(p_Sh,  CB * CH); zero_f(p_Xh,  CB * CH);
    zero_f(p_Shp, CB * CH); zero_f(p_Xhp, CB * CH);

    // ---- build CSRs ----
    k_hist<<<(E + T - 1) / T, T>>>(dst, p_cntE, E);
    k_hist<<<(M + T - 1) / T, T>>>(cc,  p_cntC, M);
    k_hist<<<(M + T - 1) / T, T>>>(cn,  p_cntN, M);
    k_scan_excl<<<1, 1024>>>(p_cntE, p_offE, p_curE, N);
    k_scan_excl<<<1, 1024>>>(p_cntC, p_offC, p_curC, KC);
    k_scan_excl<<<1, 1024>>>(p_cntN, p_offN, p_curN, N);
    k_fillE<<<(E + T - 1) / T, T>>>(src, dst, w, E);
    k_fillC<<<(M + T - 1) / T, T>>>(cn, cc, M);
    k_fillN<<<(M + T - 1) / T, T>>>(cn, cc, M);

    // ---- dinv from CSR-E ----
    k_deg_dinv<<<(N + T - 1) / T, T>>>(N);

    // ---- xw = x @ W_in ----
    sgemm128<<<(N + 127) / 128, 256>>>(x, W_in, p_xw, N, CH, nullptr);

    // ---- GCN pass 1 (gather, fused coeff/self/bias/relu) ----
    gather_gcn1<<<warpsN, T>>>(b_in, N);

    // ---- node pooling ----
    pool_sorted<<<(N + 127) / 128, CH>>>(p_h, batch, p_Sh, p_Xh, N, 128);

    // ---- cover pooling (gather add+max) ----
    gather_xp<<<warpsKC, T>>>(KC);

    // ---- aprime(ones) -> dinvp (gather chain) ----
    k_ye1g   <<<(N + T - 1) / T, T>>>(N);
    k_dinvp_g<<<(KC + T - 1) / T, T>>>(KC);

    // ---- xws = dinvp * (xp @ W_blk) ----
    sgemm128<<<(KC + 127) / 128, 256>>>(p_xp, W_blk, p_xws, KC, 2 * CH, p_dinvp);

    // ---- aprime(xws): zn = C xws ; ye = A zn ; hp = relu(dinvp*(C^T ye + xws)+b) ----
    gather_zn<<<warpsN, T>>>(N);
    gather_ye<<<warpsN, T>>>(N);
    gather_hp<<<warpsKC, T>>>(b_blk, KC);

    // ---- cluster pooling ----
    k_ccounts<<<1, 256>>>(cb, KC);
    pool_sorted<<<(KC + 127) / 128, CH>>>(p_hp, cb, p_Shp, p_Xhp, KC, 128);

    // ---- BN + MLP + softmax ----
    k_mlp<<<CB, CH>>>(gam, bet, mu, var, W1, b1, W2, b2, out);
}